// round 4
// baseline (speedup 1.0000x reference)
#include <cuda_runtime.h>

#define B_   512
#define DK_  256
#define DV_  256
#define P_   2048
#define SCALE_ (0.0625f)   // 1/sqrt(256)

// Scratch: unnormalized softmax weights + per-(batch,chunk) partial sums.
__device__ float g_attn[B_ * P_];
__device__ float g_psum[B_ * 2];

__device__ __forceinline__ float4 ldcs4(const float4* p) {
    return __ldcs(p);
}

// ---------------------------------------------------------------------------
// Kernel 1: masked, scaled energy -> exp -> partial sum.  grid (2, 512), block 256.
// K and mask are stream-once: load with .cs (evict-first) so g_attn stays in L2.
// ---------------------------------------------------------------------------
__global__ __launch_bounds__(256)
void energy_kernel(const float* __restrict__ Q,
                   const float* __restrict__ K,
                   const int*   __restrict__ mask)
{
    const int chunk = blockIdx.x;          // 0..1
    const int b     = blockIdx.y;          // 0..511
    const int tid   = threadIdx.x;
    const int lane  = tid & 31;
    const int warp  = tid >> 5;
    const int p0    = chunk * 1024 + 4 * tid;

    __shared__ float q_sh[DK_];
    __shared__ float red_sum[8];
    q_sh[tid] = Q[b * DK_ + tid];
    __syncthreads();

    const float* Kb = K + (size_t)b * DK_ * P_ + p0;
    float4 acc = make_float4(0.f, 0.f, 0.f, 0.f);

    #pragma unroll 8
    for (int d = 0; d < DK_; ++d) {
        const float4 k4 = ldcs4(reinterpret_cast<const float4*>(Kb + (size_t)d * P_));
        const float qd = q_sh[d];
        acc.x = fmaf(qd, k4.x, acc.x);
        acc.y = fmaf(qd, k4.y, acc.y);
        acc.z = fmaf(qd, k4.z, acc.z);
        acc.w = fmaf(qd, k4.w, acc.w);
    }

    const int4 m = __ldcs(reinterpret_cast<const int4*>(mask + (size_t)b * P_ + p0));
    float4 e;
    e.x = __expf(m.x ? acc.x * SCALE_ : 0.f);
    e.y = __expf(m.y ? acc.y * SCALE_ : 0.f);
    e.z = __expf(m.z ? acc.z * SCALE_ : 0.f);
    e.w = __expf(m.w ? acc.w * SCALE_ : 0.f);

    *reinterpret_cast<float4*>(g_attn + (size_t)b * P_ + p0) = e;

    // CTA partial sum of exp values
    float s = (e.x + e.y) + (e.z + e.w);
    #pragma unroll
    for (int o = 16; o; o >>= 1)
        s += __shfl_xor_sync(0xffffffffu, s, o);
    if (lane == 0) red_sum[warp] = s;
    __syncthreads();
    if (tid == 0) {
        float tot = red_sum[0];
        #pragma unroll
        for (int i = 1; i < 8; ++i) tot += red_sum[i];
        g_psum[b * 2 + chunk] = tot;
    }
}

// ---------------------------------------------------------------------------
// Kernel 2: out[b, v] = (1/sum) * sum_p w[b, p] * V[b, v, p].
// grid (8, 512), block 256.  CTA (chunk, b) handles V rows [chunk*32, +32).
// No smem staging: attn row read directly (L2-resident), V with .cs streaming.
// Warp processes 4 interleaved V rows -> 5 outstanding gmem loads/iter.
// ---------------------------------------------------------------------------
__global__ __launch_bounds__(256)
void out_kernel(const float* __restrict__ V,
                float* __restrict__ out)
{
    const int chunk = blockIdx.x;          // 0..7
    const int b     = blockIdx.y;
    const int tid   = threadIdx.x;
    const int lane  = tid & 31;
    const int warp  = tid >> 5;

    const float inv_sum = __frcp_rn(__ldg(&g_psum[b * 2]) + __ldg(&g_psum[b * 2 + 1]));

    const int vbase = chunk * 32 + warp;   // rows vbase, +8, +16, +24
    const float* Vb = V + (size_t)b * DV_ * P_;
    const float4* arow = reinterpret_cast<const float4*>(g_attn + (size_t)b * P_);
    const float4* v0r = reinterpret_cast<const float4*>(Vb + (size_t)(vbase +  0) * P_);
    const float4* v1r = reinterpret_cast<const float4*>(Vb + (size_t)(vbase +  8) * P_);
    const float4* v2r = reinterpret_cast<const float4*>(Vb + (size_t)(vbase + 16) * P_);
    const float4* v3r = reinterpret_cast<const float4*>(Vb + (size_t)(vbase + 24) * P_);

    float s0 = 0.f, s1 = 0.f, s2 = 0.f, s3 = 0.f;
    #pragma unroll
    for (int i = 0; i < 16; ++i) {
        const int idx = lane + 32 * i;
        const float4 a4 = __ldg(arow + idx);
        const float4 v0 = ldcs4(v0r + idx);
        const float4 v1 = ldcs4(v1r + idx);
        const float4 v2 = ldcs4(v2r + idx);
        const float4 v3 = ldcs4(v3r + idx);
        s0 = fmaf(a4.x, v0.x, s0); s0 = fmaf(a4.y, v0.y, s0);
        s0 = fmaf(a4.z, v0.z, s0); s0 = fmaf(a4.w, v0.w, s0);
        s1 = fmaf(a4.x, v1.x, s1); s1 = fmaf(a4.y, v1.y, s1);
        s1 = fmaf(a4.z, v1.z, s1); s1 = fmaf(a4.w, v1.w, s1);
        s2 = fmaf(a4.x, v2.x, s2); s2 = fmaf(a4.y, v2.y, s2);
        s2 = fmaf(a4.z, v2.z, s2); s2 = fmaf(a4.w, v2.w, s2);
        s3 = fmaf(a4.x, v3.x, s3); s3 = fmaf(a4.y, v3.y, s3);
        s3 = fmaf(a4.z, v3.z, s3); s3 = fmaf(a4.w, v3.w, s3);
    }

    #pragma unroll
    for (int o = 16; o; o >>= 1) {
        s0 += __shfl_xor_sync(0xffffffffu, s0, o);
        s1 += __shfl_xor_sync(0xffffffffu, s1, o);
        s2 += __shfl_xor_sync(0xffffffffu, s2, o);
        s3 += __shfl_xor_sync(0xffffffffu, s3, o);
    }
    if (lane == 0) {
        out[b * DV_ + vbase]      = s0 * inv_sum;
        out[b * DV_ + vbase + 8]  = s1 * inv_sum;
        out[b * DV_ + vbase + 16] = s2 * inv_sum;
        out[b * DV_ + vbase + 24] = s3 * inv_sum;
    }
}

extern "C" void kernel_launch(void* const* d_in, const int* in_sizes, int n_in,
                              void* d_out, int out_size)
{
    const float* Q    = (const float*)d_in[0];
    const float* K    = (const float*)d_in[1];
    const float* V    = (const float*)d_in[2];
    const int*   mask = (const int*)  d_in[3];
    float*       out  = (float*)      d_out;

    energy_kernel<<<dim3(2, B_), 256>>>(Q, K, mask);
    out_kernel<<<dim3(8, B_), 256>>>(V, out);
}

// round 5
// speedup vs baseline: 1.0059x; 1.0059x over previous
#include <cuda_runtime.h>

#define B_   512
#define DK_  256
#define DV_  256
#define P_   2048
#define SCALE_ (0.0625f)   // 1/sqrt(256)

#define N_ENERGY_CTAS 1024     // 2 chunks x 512 batches
#define N_OUT_CTAS    4096     // 8 chunks x 512 batches

// Scratch (alloc-free rule: device globals)
__device__ float g_attn[B_ * P_];
__device__ float g_psum[B_ * 2];
__device__ int   g_flag[B_];

__device__ __forceinline__ float4 ldcs4(const float4* p) { return __ldcs(p); }
__device__ __forceinline__ float4 ldcg4(const float4* p) { return __ldcg(p); }

__global__ void init_kernel()
{
    g_flag[threadIdx.x] = 0;
}

// ---------------------------------------------------------------------------
// Fused kernel. bid < 1024: energy producer (b = bid>>1, chunk = bid&1).
// bid >= 1024: output consumer (o = bid-1024, b = o>>3, chunk = o&7).
// Dispatch order guarantees every energy CTA is dispatched before any out CTA,
// so the per-batch spin-wait cannot deadlock.
// ---------------------------------------------------------------------------
__global__ __launch_bounds__(256)
void fused_kernel(const float* __restrict__ Q,
                  const float* __restrict__ K,
                  const float* __restrict__ V,
                  const int*   __restrict__ mask,
                  float* __restrict__ out)
{
    const int bid  = blockIdx.x;
    const int tid  = threadIdx.x;
    const int lane = tid & 31;
    const int warp = tid >> 5;

    if (bid < N_ENERGY_CTAS) {
        // ================= ENERGY PHASE =================
        const int b     = bid >> 1;
        const int chunk = bid & 1;
        const int p0    = chunk * 1024 + 4 * tid;

        __shared__ float q_sh[DK_];
        __shared__ float red_sum[8];
        q_sh[tid] = Q[b * DK_ + tid];
        __syncthreads();

        const float* Kb = K + (size_t)b * DK_ * P_ + p0;
        float4 acc = make_float4(0.f, 0.f, 0.f, 0.f);

        #pragma unroll 8
        for (int d = 0; d < DK_; ++d) {
            const float4 k4 = ldcs4(reinterpret_cast<const float4*>(Kb + (size_t)d * P_));
            const float qd = q_sh[d];
            acc.x = fmaf(qd, k4.x, acc.x);
            acc.y = fmaf(qd, k4.y, acc.y);
            acc.z = fmaf(qd, k4.z, acc.z);
            acc.w = fmaf(qd, k4.w, acc.w);
        }

        const int4 m = __ldcs(reinterpret_cast<const int4*>(mask + (size_t)b * P_ + p0));
        float4 e;
        e.x = __expf(m.x ? acc.x * SCALE_ : 0.f);
        e.y = __expf(m.y ? acc.y * SCALE_ : 0.f);
        e.z = __expf(m.z ? acc.z * SCALE_ : 0.f);
        e.w = __expf(m.w ? acc.w * SCALE_ : 0.f);

        *reinterpret_cast<float4*>(g_attn + (size_t)b * P_ + p0) = e;

        float s = (e.x + e.y) + (e.z + e.w);
        #pragma unroll
        for (int o = 16; o; o >>= 1)
            s += __shfl_xor_sync(0xffffffffu, s, o);
        if (lane == 0) red_sum[warp] = s;

        // release: make this thread's g_attn stores globally visible
        __threadfence();
        __syncthreads();

        if (tid == 0) {
            float tot = red_sum[0];
            #pragma unroll
            for (int i = 1; i < 8; ++i) tot += red_sum[i];
            g_psum[b * 2 + chunk] = tot;
            __threadfence();
            atomicAdd(&g_flag[b], 1);
        }
    } else {
        // ================= OUTPUT PHASE =================
        const int o_idx = bid - N_ENERGY_CTAS;
        const int b     = o_idx >> 3;
        const int chunk = o_idx & 7;

        // wait for both energy chunks of this batch
        if (tid == 0) {
            while (atomicAdd(&g_flag[b], 0) < 2) __nanosleep(200);
            __threadfence();   // acquire
        }
        __syncthreads();

        const float inv_sum = __frcp_rn(__ldcg(&g_psum[b * 2]) + __ldcg(&g_psum[b * 2 + 1]));

        const int vbase = chunk * 32 + warp;   // rows vbase, +8, +16, +24
        const float* Vb = V + (size_t)b * DV_ * P_;
        const float4* arow = reinterpret_cast<const float4*>(g_attn + (size_t)b * P_);
        const float4* v0r = reinterpret_cast<const float4*>(Vb + (size_t)(vbase +  0) * P_);
        const float4* v1r = reinterpret_cast<const float4*>(Vb + (size_t)(vbase +  8) * P_);
        const float4* v2r = reinterpret_cast<const float4*>(Vb + (size_t)(vbase + 16) * P_);
        const float4* v3r = reinterpret_cast<const float4*>(Vb + (size_t)(vbase + 24) * P_);

        float s0 = 0.f, s1 = 0.f, s2 = 0.f, s3 = 0.f;
        #pragma unroll
        for (int i = 0; i < 16; ++i) {
            const int idx = lane + 32 * i;
            const float4 a4 = ldcg4(arow + idx);   // L2-resident, never-stale path
            const float4 v0 = ldcs4(v0r + idx);
            const float4 v1 = ldcs4(v1r + idx);
            const float4 v2 = ldcs4(v2r + idx);
            const float4 v3 = ldcs4(v3r + idx);
            s0 = fmaf(a4.x, v0.x, s0); s0 = fmaf(a4.y, v0.y, s0);
            s0 = fmaf(a4.z, v0.z, s0); s0 = fmaf(a4.w, v0.w, s0);
            s1 = fmaf(a4.x, v1.x, s1); s1 = fmaf(a4.y, v1.y, s1);
            s1 = fmaf(a4.z, v1.z, s1); s1 = fmaf(a4.w, v1.w, s1);
            s2 = fmaf(a4.x, v2.x, s2); s2 = fmaf(a4.y, v2.y, s2);
            s2 = fmaf(a4.z, v2.z, s2); s2 = fmaf(a4.w, v2.w, s2);
            s3 = fmaf(a4.x, v3.x, s3); s3 = fmaf(a4.y, v3.y, s3);
            s3 = fmaf(a4.z, v3.z, s3); s3 = fmaf(a4.w, v3.w, s3);
        }

        #pragma unroll
        for (int o = 16; o; o >>= 1) {
            s0 += __shfl_xor_sync(0xffffffffu, s0, o);
            s1 += __shfl_xor_sync(0xffffffffu, s1, o);
            s2 += __shfl_xor_sync(0xffffffffu, s2, o);
            s3 += __shfl_xor_sync(0xffffffffu, s3, o);
        }
        if (lane == 0) {
            out[b * DV_ + vbase]      = s0 * inv_sum;
            out[b * DV_ + vbase + 8]  = s1 * inv_sum;
            out[b * DV_ + vbase + 16] = s2 * inv_sum;
            out[b * DV_ + vbase + 24] = s3 * inv_sum;
        }
    }
}

extern "C" void kernel_launch(void* const* d_in, const int* in_sizes, int n_in,
                              void* d_out, int out_size)
{
    const float* Q    = (const float*)d_in[0];
    const float* K    = (const float*)d_in[1];
    const float* V    = (const float*)d_in[2];
    const int*   mask = (const int*)  d_in[3];
    float*       out  = (float*)      d_out;

    init_kernel<<<1, B_>>>();
    fused_kernel<<<N_ENERGY_CTAS + N_OUT_CTAS, 256>>>(Q, K, V, mask, out);
}

// round 6
// speedup vs baseline: 1.0060x; 1.0001x over previous
#include <cuda_runtime.h>

#define B_   512
#define DK_  256
#define DV_  256
#define P_   2048
#define SCALE_ (0.0625f)   // 1/sqrt(256)

#define N_ENERGY_ITEMS 1024          // 2 chunks x 512 batches (1024 P-slots each)
#define N_OUT_ITEMS    8192          // 16 chunks x 512 batches (16 V-rows each)
#define TOTAL_ITEMS    (N_ENERGY_ITEMS + N_OUT_ITEMS)
#define N_WORKERS      888           // 148 SMs x 6 CTAs (guaranteed by launch_bounds)

// Scratch (alloc-free rule: device globals)
__device__ float        g_attn[B_ * P_];
__device__ float        g_psum[B_ * 2];
__device__ int          g_flag[B_];
__device__ unsigned int g_ctr;

__device__ __forceinline__ float4 ldcs4(const float4* p) { return __ldcs(p); }
__device__ __forceinline__ float4 ldcg4(const float4* p) { return __ldcg(p); }

__global__ void init_kernel()
{
    g_flag[threadIdx.x] = 0;
    if (threadIdx.x == 0) g_ctr = 0u;
}

// ---------------------------------------------------------------------------
// Persistent worker. Items pulled off a global atomic counter:
//   item <  1024 : energy tile  (b = item>>1, chunk = item&1, 1024 P-slots)
//   item >= 1024 : output tile  (o = item-1024, b = o>>4, c = o&15, 16 V-rows)
// Counter order => every energy item is grabbed (and thus completed by a live
// CTA) before any out item is grabbed => flag spin is deadlock-free.
// ---------------------------------------------------------------------------
__global__ __launch_bounds__(256, 6)
void worker_kernel(const float* __restrict__ Q,
                   const float* __restrict__ K,
                   const float* __restrict__ V,
                   const int*   __restrict__ mask,
                   float* __restrict__ out)
{
    const int tid  = threadIdx.x;
    const int lane = tid & 31;
    const int warp = tid >> 5;

    __shared__ float q_sh[DK_];
    __shared__ float red_sum[8];
    __shared__ int   s_item;

    for (;;) {
        __syncthreads();                       // protect s_item / q_sh reuse
        if (tid == 0) s_item = (int)atomicAdd(&g_ctr, 1u);
        __syncthreads();
        const int item = s_item;
        if (item >= TOTAL_ITEMS) return;

        if (item < N_ENERGY_ITEMS) {
            // ================= ENERGY ITEM =================
            const int b     = item >> 1;
            const int chunk = item & 1;
            const int p0    = chunk * 1024 + 4 * tid;

            q_sh[tid] = Q[b * DK_ + tid];
            __syncthreads();

            const float* Kb = K + (size_t)b * DK_ * P_ + p0;
            float4 acc = make_float4(0.f, 0.f, 0.f, 0.f);

            #pragma unroll 8
            for (int d = 0; d < DK_; ++d) {
                const float4 k4 = ldcs4(reinterpret_cast<const float4*>(Kb + (size_t)d * P_));
                const float qd = q_sh[d];
                acc.x = fmaf(qd, k4.x, acc.x);
                acc.y = fmaf(qd, k4.y, acc.y);
                acc.z = fmaf(qd, k4.z, acc.z);
                acc.w = fmaf(qd, k4.w, acc.w);
            }

            const int4 m = __ldcs(reinterpret_cast<const int4*>(mask + (size_t)b * P_ + p0));
            float4 e;
            e.x = __expf(m.x ? acc.x * SCALE_ : 0.f);
            e.y = __expf(m.y ? acc.y * SCALE_ : 0.f);
            e.z = __expf(m.z ? acc.z * SCALE_ : 0.f);
            e.w = __expf(m.w ? acc.w * SCALE_ : 0.f);

            *reinterpret_cast<float4*>(g_attn + (size_t)b * P_ + p0) = e;

            float s = (e.x + e.y) + (e.z + e.w);
            #pragma unroll
            for (int o = 16; o; o >>= 1)
                s += __shfl_xor_sync(0xffffffffu, s, o);
            if (lane == 0) red_sum[warp] = s;

            __threadfence();                   // release g_attn stores
            __syncthreads();

            if (tid == 0) {
                float tot = red_sum[0];
                #pragma unroll
                for (int i = 1; i < 8; ++i) tot += red_sum[i];
                g_psum[b * 2 + chunk] = tot;
                __threadfence();
                atomicAdd(&g_flag[b], 1);
            }
        } else {
            // ================= OUTPUT ITEM (16 V-rows) =================
            const int o_idx = item - N_ENERGY_ITEMS;
            const int b     = o_idx >> 4;
            const int c     = o_idx & 15;

            if (tid == 0) {
                while (atomicAdd(&g_flag[b], 0) < 2) __nanosleep(100);
                __threadfence();               // acquire
            }
            __syncthreads();

            const float inv_sum = __frcp_rn(__ldcg(&g_psum[b * 2]) + __ldcg(&g_psum[b * 2 + 1]));

            const int r0 = c * 16 + warp;      // rows r0 and r0+8
            const float* Vb = V + (size_t)b * DV_ * P_;
            const float4* arow = reinterpret_cast<const float4*>(g_attn + (size_t)b * P_);
            const float4* v0r = reinterpret_cast<const float4*>(Vb + (size_t)(r0 + 0) * P_);
            const float4* v1r = reinterpret_cast<const float4*>(Vb + (size_t)(r0 + 8) * P_);

            float s0 = 0.f, s1 = 0.f;
            #pragma unroll 4
            for (int i = 0; i < 16; ++i) {
                const int idx = lane + 32 * i;
                const float4 a4 = ldcg4(arow + idx);   // L2-resident
                const float4 v0 = ldcs4(v0r + idx);
                const float4 v1 = ldcs4(v1r + idx);
                s0 = fmaf(a4.x, v0.x, s0); s0 = fmaf(a4.y, v0.y, s0);
                s0 = fmaf(a4.z, v0.z, s0); s0 = fmaf(a4.w, v0.w, s0);
                s1 = fmaf(a4.x, v1.x, s1); s1 = fmaf(a4.y, v1.y, s1);
                s1 = fmaf(a4.z, v1.z, s1); s1 = fmaf(a4.w, v1.w, s1);
            }

            #pragma unroll
            for (int o = 16; o; o >>= 1) {
                s0 += __shfl_xor_sync(0xffffffffu, s0, o);
                s1 += __shfl_xor_sync(0xffffffffu, s1, o);
            }
            if (lane == 0) {
                out[b * DV_ + r0]     = s0 * inv_sum;
                out[b * DV_ + r0 + 8] = s1 * inv_sum;
            }
        }
    }
}

extern "C" void kernel_launch(void* const* d_in, const int* in_sizes, int n_in,
                              void* d_out, int out_size)
{
    const float* Q    = (const float*)d_in[0];
    const float* K    = (const float*)d_in[1];
    const float* V    = (const float*)d_in[2];
    const int*   mask = (const int*)  d_in[3];
    float*       out  = (float*)      d_out;

    init_kernel<<<1, B_>>>();
    worker_kernel<<<N_WORKERS, 256>>>(Q, K, V, mask, out);
}

// round 8
// speedup vs baseline: 1.0119x; 1.0059x over previous
#include <cuda_runtime.h>
#include <cuda_fp16.h>

#define B_   512
#define DK_  256
#define DV_  256
#define P_   2048
#define SCALE_ (0.0625f)   // 1/sqrt(256)

#define N_ENERGY_ITEMS 1024          // 2 chunks x 512 batches (1024 P-slots each)
#define N_OUT_ITEMS    4096          // 8 chunks x 512 batches (32 V-rows each)
#define TOTAL_ITEMS    (N_ENERGY_ITEMS + N_OUT_ITEMS)
#define N_WORKERS      888           // 148 SMs x 6 CTAs

// Scratch (alloc-free rule: device globals). Attn weights stored as fp16.
__device__ __half       g_attn_h[B_ * P_];
__device__ float        g_psum[B_ * 2];
__device__ int          g_flag[B_];
__device__ unsigned int g_ctr;

__device__ __forceinline__ float4 ldcs4(const float4* p) { return __ldcs(p); }

__global__ void init_kernel()
{
    g_flag[threadIdx.x] = 0;
    if (threadIdx.x == 0) g_ctr = 0u;
}

// ---------------------------------------------------------------------------
// Persistent worker. Items off a global atomic counter:
//   item <  1024 : energy tile (b = item>>1, chunk = item&1, 1024 P-slots)
//   item >= 1024 : output tile (o = item-1024, b = o>>3, c = o&7, 32 V-rows)
// Counter order => all energy items grabbed (by live CTAs) before any out item
// => per-batch flag spin is deadlock-free.
// ---------------------------------------------------------------------------
__global__ __launch_bounds__(256, 6)
void worker_kernel(const float* __restrict__ Q,
                   const float* __restrict__ K,
                   const float* __restrict__ V,
                   const int*   __restrict__ mask,
                   float* __restrict__ out)
{
    const int tid  = threadIdx.x;
    const int lane = tid & 31;
    const int warp = tid >> 5;

    __shared__ float q_sh[DK_];
    __shared__ float red_sum[8];
    __shared__ int   s_item;

    for (;;) {
        __syncthreads();                       // protect s_item / q_sh reuse
        if (tid == 0) s_item = (int)atomicAdd(&g_ctr, 1u);
        __syncthreads();
        const int item = s_item;
        if (item >= TOTAL_ITEMS) return;

        if (item < N_ENERGY_ITEMS) {
            // ================= ENERGY ITEM =================
            const int b     = item >> 1;
            const int chunk = item & 1;
            const int p0    = chunk * 1024 + 4 * tid;

            q_sh[tid] = Q[b * DK_ + tid];
            __syncthreads();

            const float* Kb = K + (size_t)b * DK_ * P_ + p0;
            float4 acc = make_float4(0.f, 0.f, 0.f, 0.f);

            #pragma unroll 8
            for (int d = 0; d < DK_; ++d) {
                const float4 k4 = ldcs4(reinterpret_cast<const float4*>(Kb + (size_t)d * P_));
                const float qd = q_sh[d];
                acc.x = fmaf(qd, k4.x, acc.x);
                acc.y = fmaf(qd, k4.y, acc.y);
                acc.z = fmaf(qd, k4.z, acc.z);
                acc.w = fmaf(qd, k4.w, acc.w);
            }

            const int4 m = __ldcs(reinterpret_cast<const int4*>(mask + (size_t)b * P_ + p0));
            float4 e;
            e.x = __expf(m.x ? acc.x * SCALE_ : 0.f);
            e.y = __expf(m.y ? acc.y * SCALE_ : 0.f);
            e.z = __expf(m.z ? acc.z * SCALE_ : 0.f);
            e.w = __expf(m.w ? acc.w * SCALE_ : 0.f);

            // round to fp16, store packed, and sum the ROUNDED values so the
            // normalizer matches the stored weights exactly
            const __half2 h01 = __floats2half2_rn(e.x, e.y);
            const __half2 h23 = __floats2half2_rn(e.z, e.w);
            uint2 packed;
            packed.x = *reinterpret_cast<const unsigned int*>(&h01);
            packed.y = *reinterpret_cast<const unsigned int*>(&h23);
            *reinterpret_cast<uint2*>(g_attn_h + (size_t)b * P_ + p0) = packed;

            const float2 f01 = __half22float2(h01);
            const float2 f23 = __half22float2(h23);
            float s = (f01.x + f01.y) + (f23.x + f23.y);
            #pragma unroll
            for (int o = 16; o; o >>= 1)
                s += __shfl_xor_sync(0xffffffffu, s, o);
            if (lane == 0) red_sum[warp] = s;

            __threadfence();                   // release g_attn stores
            __syncthreads();

            if (tid == 0) {
                float tot = red_sum[0];
                #pragma unroll
                for (int i = 1; i < 8; ++i) tot += red_sum[i];
                g_psum[b * 2 + chunk] = tot;
                __threadfence();
                atomicAdd(&g_flag[b], 1);
            }
        } else {
            // ================= OUTPUT ITEM (32 V-rows, 4 rows/warp) =================
            const int o_idx = item - N_ENERGY_ITEMS;
            const int b     = o_idx >> 3;
            const int c     = o_idx & 7;

            if (tid == 0) {
                while (atomicAdd(&g_flag[b], 0) < 2) __nanosleep(100);
                __threadfence();               // acquire
            }
            __syncthreads();

            const float inv_sum = __frcp_rn(__ldcg(&g_psum[b * 2]) + __ldcg(&g_psum[b * 2 + 1]));

            const int vbase = c * 32 + warp;   // rows vbase, +8, +16, +24
            const float* Vb = V + (size_t)b * DV_ * P_;
            const uint2*  arow = reinterpret_cast<const uint2*>(g_attn_h + (size_t)b * P_);
            const float4* v0r = reinterpret_cast<const float4*>(Vb + (size_t)(vbase +  0) * P_);
            const float4* v1r = reinterpret_cast<const float4*>(Vb + (size_t)(vbase +  8) * P_);
            const float4* v2r = reinterpret_cast<const float4*>(Vb + (size_t)(vbase + 16) * P_);
            const float4* v3r = reinterpret_cast<const float4*>(Vb + (size_t)(vbase + 24) * P_);

            float s0 = 0.f, s1 = 0.f, s2 = 0.f, s3 = 0.f;
            #pragma unroll 4
            for (int i = 0; i < 16; ++i) {
                const int idx = lane + 32 * i;          // 4 p per idx
                const uint2 ap = __ldcg(arow + idx);    // L2-resident, bypass L1
                const __half2 h01 = *reinterpret_cast<const __half2*>(&ap.x);
                const __half2 h23 = *reinterpret_cast<const __half2*>(&ap.y);
                const float2 a01 = __half22float2(h01);
                const float2 a23 = __half22float2(h23);
                const float4 v0 = ldcs4(v0r + idx);
                const float4 v1 = ldcs4(v1r + idx);
                const float4 v2 = ldcs4(v2r + idx);
                const float4 v3 = ldcs4(v3r + idx);
                s0 = fmaf(a01.x, v0.x, s0); s0 = fmaf(a01.y, v0.y, s0);
                s0 = fmaf(a23.x, v0.z, s0); s0 = fmaf(a23.y, v0.w, s0);
                s1 = fmaf(a01.x, v1.x, s1); s1 = fmaf(a01.y, v1.y, s1);
                s1 = fmaf(a23.x, v1.z, s1); s1 = fmaf(a23.y, v1.w, s1);
                s2 = fmaf(a01.x, v2.x, s2); s2 = fmaf(a01.y, v2.y, s2);
                s2 = fmaf(a23.x, v2.z, s2); s2 = fmaf(a23.y, v2.w, s2);
                s3 = fmaf(a01.x, v3.x, s3); s3 = fmaf(a01.y, v3.y, s3);
                s3 = fmaf(a23.x, v3.z, s3); s3 = fmaf(a23.y, v3.w, s3);
            }

            #pragma unroll
            for (int o = 16; o; o >>= 1) {
                s0 += __shfl_xor_sync(0xffffffffu, s0, o);
                s1 += __shfl_xor_sync(0xffffffffu, s1, o);
                s2 += __shfl_xor_sync(0xffffffffu, s2, o);
                s3 += __shfl_xor_sync(0xffffffffu, s3, o);
            }
            if (lane == 0) {
                out[b * DV_ + vbase]      = s0 * inv_sum;
                out[b * DV_ + vbase + 8]  = s1 * inv_sum;
                out[b * DV_ + vbase + 16] = s2 * inv_sum;
                out[b * DV_ + vbase + 24] = s3 * inv_sum;
            }
        }
    }
}

extern "C" void kernel_launch(void* const* d_in, const int* in_sizes, int n_in,
                              void* d_out, int out_size)
{
    const float* Q    = (const float*)d_in[0];
    const float* K    = (const float*)d_in[1];
    const float* V    = (const float*)d_in[2];
    const int*   mask = (const int*)  d_in[3];
    float*       out  = (float*)      d_out;

    init_kernel<<<1, B_>>>();
    worker_kernel<<<N_WORKERS, 256>>>(Q, K, V, mask, out);
}

// round 9
// speedup vs baseline: 1.0266x; 1.0145x over previous
#include <cuda_runtime.h>
#include <cuda_fp16.h>

#define B_   512
#define DK_  256
#define DV_  256
#define P_   2048
#define SCALE_ (0.0625f)   // 1/sqrt(256)

#define N_ENERGY_ITEMS 1024          // 2 chunks x 512 batches (1024 P-slots each)
#define N_OUT_ITEMS    4096          // 8 chunks x 512 batches (32 V-rows each)
#define TOTAL_ITEMS    (N_ENERGY_ITEMS + N_OUT_ITEMS)
#define N_WORKERS      888           // 148 SMs x 6 CTAs

// Scratch (alloc-free rule: device globals). Zero-initialized at module load;
// the kernel restores the zero state itself before exiting (self-resetting),
// so no init kernel is needed and the graph is a single node.
__device__ __half       g_attn_h[B_ * P_];
__device__ float        g_psum[B_ * 2];
__device__ int          g_flag[B_];
__device__ unsigned int g_ctr;
__device__ unsigned int g_done;

__device__ __forceinline__ float4 ldcs4(const float4* p) { return __ldcs(p); }

// ---------------------------------------------------------------------------
// Persistent worker. Items off a global atomic counter:
//   item <  1024 : energy tile (b = item>>1, chunk = item&1, 1024 P-slots)
//   item >= 1024 : output tile (o = item-1024, b = o>>3, c = o&7, 32 V-rows)
// Counter order => all energy items grabbed (by live CTAs) before any out item
// => per-batch flag spin is deadlock-free.
// The LAST CTA to exhaust the queue resets all state for the next replay
// (all work is complete at that point; kernel boundary publishes the stores).
// ---------------------------------------------------------------------------
__global__ __launch_bounds__(256, 6)
void worker_kernel(const float* __restrict__ Q,
                   const float* __restrict__ K,
                   const float* __restrict__ V,
                   const int*   __restrict__ mask,
                   float* __restrict__ out)
{
    const int tid  = threadIdx.x;
    const int lane = tid & 31;
    const int warp = tid >> 5;

    __shared__ float q_sh[DK_];
    __shared__ float red_sum[8];
    __shared__ int   s_item;

    for (;;) {
        __syncthreads();                       // protect s_item / q_sh reuse
        if (tid == 0) s_item = (int)atomicAdd(&g_ctr, 1u);
        __syncthreads();
        const int item = s_item;
        if (item >= TOTAL_ITEMS) break;

        if (item < N_ENERGY_ITEMS) {
            // ================= ENERGY ITEM =================
            const int b     = item >> 1;
            const int chunk = item & 1;
            const int p0    = chunk * 1024 + 4 * tid;

            q_sh[tid] = Q[b * DK_ + tid];
            __syncthreads();

            const float* Kb = K + (size_t)b * DK_ * P_ + p0;
            float4 acc = make_float4(0.f, 0.f, 0.f, 0.f);

            #pragma unroll 8
            for (int d = 0; d < DK_; ++d) {
                const float4 k4 = ldcs4(reinterpret_cast<const float4*>(Kb + (size_t)d * P_));
                const float qd = q_sh[d];
                acc.x = fmaf(qd, k4.x, acc.x);
                acc.y = fmaf(qd, k4.y, acc.y);
                acc.z = fmaf(qd, k4.z, acc.z);
                acc.w = fmaf(qd, k4.w, acc.w);
            }

            const int4 m = __ldcs(reinterpret_cast<const int4*>(mask + (size_t)b * P_ + p0));
            float4 e;
            e.x = __expf(m.x ? acc.x * SCALE_ : 0.f);
            e.y = __expf(m.y ? acc.y * SCALE_ : 0.f);
            e.z = __expf(m.z ? acc.z * SCALE_ : 0.f);
            e.w = __expf(m.w ? acc.w * SCALE_ : 0.f);

            // round to fp16, store packed; sum the ROUNDED values so the
            // normalizer matches the stored weights exactly
            const __half2 h01 = __floats2half2_rn(e.x, e.y);
            const __half2 h23 = __floats2half2_rn(e.z, e.w);
            uint2 packed;
            packed.x = *reinterpret_cast<const unsigned int*>(&h01);
            packed.y = *reinterpret_cast<const unsigned int*>(&h23);
            *reinterpret_cast<uint2*>(g_attn_h + (size_t)b * P_ + p0) = packed;

            const float2 f01 = __half22float2(h01);
            const float2 f23 = __half22float2(h23);
            float s = (f01.x + f01.y) + (f23.x + f23.y);
            #pragma unroll
            for (int o = 16; o; o >>= 1)
                s += __shfl_xor_sync(0xffffffffu, s, o);
            if (lane == 0) red_sum[warp] = s;

            __threadfence();                   // release g_attn stores
            __syncthreads();

            if (tid == 0) {
                float tot = red_sum[0];
                #pragma unroll
                for (int i = 1; i < 8; ++i) tot += red_sum[i];
                g_psum[b * 2 + chunk] = tot;
                __threadfence();
                atomicAdd(&g_flag[b], 1);
            }
        } else {
            // ================= OUTPUT ITEM (32 V-rows, 4 rows/warp) =================
            const int o_idx = item - N_ENERGY_ITEMS;
            const int b     = o_idx >> 3;
            const int c     = o_idx & 7;

            if (tid == 0) {
                while (__ldcg((const int*)&g_flag[b]) < 2) __nanosleep(100);
                __threadfence();               // acquire
            }
            __syncthreads();

            const float inv_sum = __frcp_rn(__ldcg(&g_psum[b * 2]) + __ldcg(&g_psum[b * 2 + 1]));

            const int vbase = c * 32 + warp;   // rows vbase, +8, +16, +24
            const float* Vb = V + (size_t)b * DV_ * P_;
            const uint2*  arow = reinterpret_cast<const uint2*>(g_attn_h + (size_t)b * P_);
            const float4* v0r = reinterpret_cast<const float4*>(Vb + (size_t)(vbase +  0) * P_);
            const float4* v1r = reinterpret_cast<const float4*>(Vb + (size_t)(vbase +  8) * P_);
            const float4* v2r = reinterpret_cast<const float4*>(Vb + (size_t)(vbase + 16) * P_);
            const float4* v3r = reinterpret_cast<const float4*>(Vb + (size_t)(vbase + 24) * P_);

            float s0 = 0.f, s1 = 0.f, s2 = 0.f, s3 = 0.f;
            #pragma unroll 4
            for (int i = 0; i < 16; ++i) {
                const int idx = lane + 32 * i;          // 4 p per idx
                const uint2 ap = __ldcg(arow + idx);    // L2-resident, bypass L1
                const __half2 h01 = *reinterpret_cast<const __half2*>(&ap.x);
                const __half2 h23 = *reinterpret_cast<const __half2*>(&ap.y);
                const float2 a01 = __half22float2(h01);
                const float2 a23 = __half22float2(h23);
                const float4 v0 = ldcs4(v0r + idx);
                const float4 v1 = ldcs4(v1r + idx);
                const float4 v2 = ldcs4(v2r + idx);
                const float4 v3 = ldcs4(v3r + idx);
                s0 = fmaf(a01.x, v0.x, s0); s0 = fmaf(a01.y, v0.y, s0);
                s0 = fmaf(a23.x, v0.z, s0); s0 = fmaf(a23.y, v0.w, s0);
                s1 = fmaf(a01.x, v1.x, s1); s1 = fmaf(a01.y, v1.y, s1);
                s1 = fmaf(a23.x, v1.z, s1); s1 = fmaf(a23.y, v1.w, s1);
                s2 = fmaf(a01.x, v2.x, s2); s2 = fmaf(a01.y, v2.y, s2);
                s2 = fmaf(a23.x, v2.z, s2); s2 = fmaf(a23.y, v2.w, s2);
                s3 = fmaf(a01.x, v3.x, s3); s3 = fmaf(a01.y, v3.y, s3);
                s3 = fmaf(a23.x, v3.z, s3); s3 = fmaf(a23.y, v3.w, s3);
            }

            #pragma unroll
            for (int o = 16; o; o >>= 1) {
                s0 += __shfl_xor_sync(0xffffffffu, s0, o);
                s1 += __shfl_xor_sync(0xffffffffu, s1, o);
                s2 += __shfl_xor_sync(0xffffffffu, s2, o);
                s3 += __shfl_xor_sync(0xffffffffu, s3, o);
            }
            if (lane == 0) {
                out[b * DV_ + vbase]      = s0 * inv_sum;
                out[b * DV_ + vbase + 8]  = s1 * inv_sum;
                out[b * DV_ + vbase + 16] = s2 * inv_sum;
                out[b * DV_ + vbase + 24] = s3 * inv_sum;
            }
        }
    }

    // ---- self-reset for next graph replay: last CTA out restores zero state ----
    if (tid == 0) {
        __threadfence();
        const unsigned int d = atomicAdd(&g_done, 1u);
        if (d == N_WORKERS - 1) {              // all work complete, all CTAs exiting
            for (int i = 0; i < B_; ++i) g_flag[i] = 0;
            g_ctr  = 0u;
            g_done = 0u;
            __threadfence();
        }
    }
}

extern "C" void kernel_launch(void* const* d_in, const int* in_sizes, int n_in,
                              void* d_out, int out_size)
{
    const float* Q    = (const float*)d_in[0];
    const float* K    = (const float*)d_in[1];
    const float* V    = (const float*)d_in[2];
    const int*   mask = (const int*)  d_in[3];
    float*       out  = (float*)      d_out;

    worker_kernel<<<N_WORKERS, 256>>>(Q, K, V, mask, out);
}